// round 10
// baseline (speedup 1.0000x reference)
#include <cuda_runtime.h>
#include <cuda_bf16.h>
#include <cstdint>

#define Bb   16
#define LAT  8
#define NPTS 500000
#define XS   256
#define IMG_ELEMS (Bb * XS * XS)   // 1,048,576
#define NXH  129                   // Hermitian half-spectrum width
#define SSTR 132                   // g_S row stride (float2)

// ---------------- device scratch (static, no runtime allocation) ------------
__device__ float  g_img[IMG_ELEMS];            // 4 MB (scatter accumulator)
__device__ float  g_tmp[IMG_ELEMS];            // 4 MB (y-blurred image)
__device__ float2 g_S[Bb * XS * SSTR];         // 4.3 MB half spectrum [b][y][x]
__device__ float  g_R[Bb * 6];
__device__ float  g_sh[Bb * 2];
__device__ float  g_h[Bb * LAT];
__device__ float2 g_tw[128];                   // exp(-2*pi*i*k/256)

#define REV8(i) ((int)(__brev((unsigned)(i)) >> 24))
__device__ __constant__ int BR4[16] = {0,8,4,12,2,10,6,14,1,9,5,13,3,11,7,15};

__device__ __forceinline__ float2 cmul(float2 a, float2 b)
{ return make_float2(a.x*b.x - a.y*b.y, a.x*b.y + a.y*b.x); }
__device__ __forceinline__ float2 cmulc(float2 a, float2 b)   // a * conj(b)
{ return make_float2(a.x*b.x + a.y*b.y, a.y*b.x - a.x*b.y); }

__device__ __forceinline__ float2 twget(const float2* stw, int idx)
{
    idx &= 255;
    float2 w = stw[idx & 127];
    if (idx & 128) w = make_float2(-w.x, -w.y);
    return w;
}

// ---------------- prep (bit-identical to passing version) -------------------
__global__ void prep_kernel(const float* __restrict__ rows,
                            const float* __restrict__ shifts,
                            const float* __restrict__ latent,
                            const float* __restrict__ W0, const float* __restrict__ b0,
                            const float* __restrict__ W1, const float* __restrict__ b1,
                            const float* __restrict__ W2, const float* __restrict__ b2,
                            const float* __restrict__ W3, const float* __restrict__ b3)
{
    int t = threadIdx.x;
    if (t < 128) {
        float ang = -6.283185307179586f * (float)t / 256.0f;
        float s, c;
        sincosf(ang, &s, &c);
        g_tw[t] = make_float2(c, s);
    }
    if (t < Bb) {
        int b = t;
        float rot = rows[b*3+0], tilt = rows[b*3+1], psi = rows[b*3+2];
        float ca = cosf(rot),  sa = sinf(rot);
        float cb = cosf(tilt), sb = sinf(tilt);
        float cg = cosf(psi),  sg = sinf(psi);
        float cgcb = __fmul_rn(cg, cb);
        g_R[b*6+0] = __fsub_rn(__fmul_rn(cgcb, ca), __fmul_rn(sg, sa));
        g_R[b*6+1] = __fadd_rn(__fmul_rn(cgcb, sa), __fmul_rn(sg, ca));
        g_R[b*6+2] = __fmul_rn(-cg, sb);
        float msgcb = __fmul_rn(-sg, cb);
        g_R[b*6+3] = __fsub_rn(__fmul_rn(msgcb, ca), __fmul_rn(cg, sa));
        g_R[b*6+4] = __fadd_rn(__fmul_rn(msgcb, sa), __fmul_rn(cg, ca));
        g_R[b*6+5] = __fmul_rn(sg, sb);
        g_sh[b*2+0] = shifts[b*2+0];
        g_sh[b*2+1] = shifts[b*2+1];

        float h[LAT], l[LAT], tv[LAT];
        for (int i = 0; i < LAT; i++) l[i] = latent[b*LAT+i];
        for (int j = 0; j < LAT; j++) {
            float acc = 0.0f;
            for (int i = 0; i < LAT; i++) acc = __fmaf_rn(l[i], W0[i*LAT+j], acc);
            acc = __fadd_rn(acc, b0[j]);
            h[j] = sinf(30.0f * acc);
        }
        const float* Ws[3] = {W1, W2, W3};
        const float* bs[3] = {b1, b2, b3};
        for (int L = 0; L < 3; L++) {
            for (int j = 0; j < LAT; j++) {
                float acc = 0.0f;
                for (int i = 0; i < LAT; i++) acc = __fmaf_rn(h[i], Ws[L][i*LAT+j], acc);
                acc = __fadd_rn(acc, bs[L][j]);
                tv[j] = sinf(acc);
            }
            for (int j = 0; j < LAT; j++) h[j] = __fadd_rn(h[j], tv[j]);
        }
        for (int j = 0; j < LAT; j++) g_h[b*LAT+j] = h[j];
    }
}

// ---------------- zero image (vectorized) ------------------------------------
__global__ void zero_kernel()
{
    int i = blockIdx.x * blockDim.x + threadIdx.x;
    reinterpret_cast<float4*>(g_img)[i] = make_float4(0.f, 0.f, 0.f, 0.f);
}

// ---------------- scatter (bit-identical to passing version) ----------------
__global__ void scatter_kernel(const float* __restrict__ coords,
                               const float* __restrict__ values,
                               const float* __restrict__ Wd,
                               const float* __restrict__ bd)
{
    __shared__ float sR[Bb*6], sSh[Bb*2], sH[Bb*LAT];
    int t = threadIdx.x;
    if (t < Bb*6)   sR[t]  = g_R[t];
    if (t < Bb*2)   sSh[t] = g_sh[t];
    if (t < Bb*LAT) sH[t]  = g_h[t];
    __syncthreads();

    int n = blockIdx.x * blockDim.x + t;
    if (n >= NPTS) return;

    float c0 = coords[3*n+0];
    float c1 = coords[3*n+1];
    float c2 = coords[3*n+2];
    float val = values[n];
    float bdn = bd[n];

    float wd[LAT];
#pragma unroll
    for (int l = 0; l < LAT; l++) wd[l] = Wd[l*NPTS + n];

#pragma unroll
    for (int b = 0; b < Bb; b++) {
        float x = __fmul_rn(sR[b*6+0], c0);
        x = __fmaf_rn(sR[b*6+1], c1, x);
        x = __fmaf_rn(sR[b*6+2], c2, x);
        float y = __fmul_rn(sR[b*6+3], c0);
        y = __fmaf_rn(sR[b*6+4], c1, y);
        y = __fmaf_rn(sR[b*6+5], c2, y);
        x = __fadd_rn(__fadd_rn(x, sSh[b*2+0]), 128.0f);
        y = __fadd_rn(__fadd_rn(y, sSh[b*2+1]), 128.0f);
        float pxf = fminf(fmaxf(rintf(x), 0.0f), 255.0f);
        float pyf = fminf(fmaxf(rintf(y), 0.0f), 255.0f);
        int px = (int)pxf;
        int py = (int)pyf;

        float d = 0.0f;
#pragma unroll
        for (int l = 0; l < LAT; l++) d = __fmaf_rn(sH[b*LAT+l], wd[l], d);
        float contrib = __fadd_rn(val, __fadd_rn(d, bdn));

        int idx = (b << 16) | (py << 8) | px;
        atomicAdd(&g_img[idx], contrib);
    }
}

// ---------------- register-resident FFT16 (DIF, bitrev output) --------------
__device__ __forceinline__ void fft16_dif(float2* r, const float2* stw, bool conj_tw)
{
#pragma unroll
    for (int st = 0; st < 4; st++) {
        int half = 8 >> st;
#pragma unroll
        for (int base = 0; base < 16; base += 16 >> st) {
#pragma unroll
            for (int k = 0; k < 8; k++) {
                if (k < half) {
                    int i0 = base + k, i1 = i0 + half;
                    float2 u = r[i0], v = r[i1];
                    r[i0] = make_float2(u.x + v.x, u.y + v.y);
                    float2 d = make_float2(u.x - v.x, u.y - v.y);
                    float2 tw = stw[k << (4 + st)];      // W16^(k*2^st)
                    r[i1] = conj_tw ? cmulc(d, tw) : cmul(d, tw);
                }
            }
        }
    }
}

// DIT with conjugate twiddles: bit-reversed input -> natural output (inverse).
__device__ __forceinline__ void fft16_dit_conj(float2* r, const float2* stw)
{
#pragma unroll
    for (int st = 0; st < 4; st++) {
        int half = 1 << st;
#pragma unroll
        for (int base = 0; base < 16; base += 2 << st) {
#pragma unroll
            for (int k = 0; k < 8; k++) {
                if (k < half) {
                    int i0 = base + k, i1 = i0 + half;
                    float2 tw = stw[k << (7 - st)];
                    float2 u = r[i0];
                    float2 t = cmulc(r[i1], tw);
                    r[i0] = make_float2(u.x + t.x, u.y + t.y);
                    r[i1] = make_float2(u.x - t.x, u.y - t.y);
                }
            }
        }
    }
}

// ---------------- blur weights ------------------------------------------------
#define GW0 0.39905027f
#define GW1 0.24203622f
#define GW2 0.05400558f
#define GW3 0.00443305f

// ---------------- y-blur, register rolling window ----------------------------
// thread = one x column, 8 outputs. grid Bb*32 x 256. MAC order d-ascending,
// zero outside image (bit-identical to previous passing blur).
__global__ void blur_y_reg()
{
    const float w[7] = {GW3, GW2, GW1, GW0, GW1, GW2, GW3};
    int tid = threadIdx.x;               // x = tid
    int bid = blockIdx.x;                // Bb*32
    int b  = bid >> 5;
    int y0 = (bid & 31) << 3;
    int bbase = b << 16;

    float v[14];
#pragma unroll
    for (int k = 0; k < 14; k++) {
        int gy = y0 + k - 3;
        v[k] = (gy >= 0 && gy < XS) ? g_img[bbase | (gy << 8) | tid] : 0.0f;
    }
#pragma unroll
    for (int r = 0; r < 8; r++) {
        float acc = 0.0f;
#pragma unroll
        for (int d = 0; d < 7; d++)
            acc += w[d] * v[r + d];
        g_tmp[bbase | ((y0 + r) << 8) | tid] = acc;
    }
}

// ---------------- x-blur + packed forward row FFT, 8 pairs/block -------------
// 128 threads, all active in FFT (8 pairs x 16 roles). grid Bb*16 = 256.
__global__ void fwd_fft_rows()
{
    __shared__ __align__(16) char smb[16896 + 16640];
    float*  ybl   = (float*)smb;                    // 16 x 264 floats
    float2* zbuf  = (float2*)smb;                   // alias ybl: 8 x 260 float2
    float2* stage = (float2*)(smb + 16896);         // 8 x 260 float2
    __shared__ float2 stw[128];
    const float w[7] = {GW3, GW2, GW1, GW0, GW1, GW2, GW3};

    int tid = threadIdx.x;               // 128 threads
    int bid = blockIdx.x;                // Bb*16
    int b  = bid >> 4;
    int y0 = (bid & 15) << 4;
    int bbase = b << 16;

    stw[tid] = g_tw[tid];
    if (tid < 96) {                      // zero ybl col borders (16 rows x 6)
        int r = tid / 6, p = tid - r * 6;
        int col = (p < 3) ? p : (256 + p);
        ybl[r * 264 + col] = 0.0f;
    }
    // load 16 y-blurred rows (float4 coalesced; scalar STS due to +3 offset)
    const float4* tmp4 = reinterpret_cast<const float4*>(g_tmp);
    for (int i = tid; i < 16 * 64; i += 128) {
        int r = i >> 6, c4 = i & 63;
        float4 v = tmp4[(b << 14) | ((y0 + r) << 6) | c4];
        float* dst = ybl + r * 264 + 3 + (c4 << 2);
        dst[0] = v.x; dst[1] = v.y; dst[2] = v.z; dst[3] = v.w;
    }
    __syncthreads();

    // x-pass + pack row pairs into complex rows
    for (int i = tid; i < 8 * 256; i += 128) {
        int g = i >> 8, c = i & 255;
        float a0 = 0.0f, a1 = 0.0f;
#pragma unroll
        for (int d = 0; d < 7; d++) {
            a0 += w[d] * ybl[(2 * g)     * 264 + c + d];
            a1 += w[d] * ybl[(2 * g + 1) * 264 + c + d];
        }
        stage[g * 260 + c] = make_float2(a0, a1);
    }
    __syncthreads();

    // four-step FFT256 on 8 pairs: g = tid>>4, t = tid&15 (all 128 active)
    int g = tid >> 4, t = tid & 15;
    float2 r[16];
#pragma unroll
    for (int n1 = 0; n1 < 16; n1++)
        r[n1] = stage[g * 260 + (n1 << 4) + t];
    fft16_dif(r, stw, false);            // reg i: A[k1 = BR4[i]]
    // thread owns column t exclusively -> safe in-place transpose write
#pragma unroll
    for (int i = 0; i < 16; i++) {
        int k1 = BR4[i];
        stage[g * 260 + (k1 << 4) + t] = cmul(r[i], twget(stw, t * k1));
    }
    __syncthreads();

    float2 c[16];
#pragma unroll
    for (int n2 = 0; n2 < 16; n2++)      // thread role: k1 = t
        c[n2] = stage[g * 260 + (t << 4) + n2];
    fft16_dif(c, stw, false);            // reg i: Z[k = t + 16*BR4[i]]
    __syncthreads();                     // ybl reads all done; zbuf aliases ybl
#pragma unroll
    for (int i = 0; i < 16; i++)
        zbuf[g * 260 + (BR4[i] << 4) + t] = c[i];
    __syncthreads();

    // Hermitian unpack; coalesced stores (8 pairs x 128 x-values)
    for (int i = tid; i < 8 * 128; i += 128) {
        int gg = i >> 7, x = i & 127;
        float2 Z  = zbuf[gg * 260 + x];
        float2 Zm = zbuf[gg * 260 + ((256 - x) & 255)];
        float2 F0 = make_float2(0.5f * (Z.x + Zm.x), 0.5f * (Z.y - Zm.y));
        float2 F1 = make_float2(0.5f * (Z.y + Zm.y), 0.5f * (Zm.x - Z.x));
        int r0 = (b * 256 + y0 + 2 * gg) * SSTR;
        g_S[r0 + x]        = F0;
        g_S[r0 + SSTR + x] = F1;
    }
    if (tid < 8) {                       // x = 128 (Nyquist)
        float2 Zn = zbuf[tid * 260 + 128];
        int r0 = (b * 256 + y0 + 2 * tid) * SSTR;
        g_S[r0 + 128]        = make_float2(Zn.x, 0.0f);
        g_S[r0 + SSTR + 128] = make_float2(Zn.y, 0.0f);
    }
}

// ---------------- column pipeline: four-step 16x16, 16 x-cols per block ------
__global__ void fft_cols_ctf_k(const float* __restrict__ ctf)
{
    __shared__ float2 sm[256 * 17];
    __shared__ float2 stw[128];
    int t  = threadIdx.x;                 // 256
    int xi = t & 15, tb = t >> 4;
    int bid = blockIdx.x;                 // b*9 + tile
    int b = bid / 9, tile = bid - b * 9;
    int x = (tile << 4) + xi;
    bool xok = (x <= 128);
    if (t < 128) stw[t] = g_tw[t];
    __syncthreads();

    float2 r[16];
#pragma unroll
    for (int n1 = 0; n1 < 16; n1++)
        r[n1] = xok ? g_S[(b * 256 + (n1 << 4) + tb) * SSTR + x]
                    : make_float2(0.f, 0.f);
    fft16_dif(r, stw, false);

#pragma unroll
    for (int i = 0; i < 16; i++) {
        int k1 = BR4[i];
        sm[(k1 * 16 + tb) * 17 + xi] = cmul(r[i], twget(stw, tb * k1));
    }
    __syncthreads();

    float2 c[16];
#pragma unroll
    for (int n2 = 0; n2 < 16; n2++)
        c[n2] = sm[(tb * 16 + n2) * 17 + xi];
    fft16_dif(c, stw, false);

#pragma unroll
    for (int i = 0; i < 16; i++) {
        int y = tb + (BR4[i] << 4);
        float cc = xok ? ctf[(b * 256 + y) * NXH + x] : 0.0f;
        c[i].x *= cc; c[i].y *= cc;
    }

    fft16_dit_conj(c, stw);
#pragma unroll
    for (int n2 = 0; n2 < 16; n2++)
        c[n2] = cmulc(c[n2], twget(stw, tb * n2));
    __syncthreads();
#pragma unroll
    for (int n2 = 0; n2 < 16; n2++)
        sm[(n2 * 16 + tb) * 17 + xi] = c[n2];
    __syncthreads();

    float2 e[16];
#pragma unroll
    for (int k1 = 0; k1 < 16; k1++)
        e[k1] = sm[(tb * 16 + k1) * 17 + xi];
    fft16_dif(e, stw, true);

#pragma unroll
    for (int i = 0; i < 16; i++) {
        int y = (BR4[i] << 4) + tb;
        if (xok) g_S[(b * 256 + y) * SSTR + x] = e[i];
    }
}

// ---------------- inverse row FFT: four-step, 16 rows/block, all-active ------
// 128 threads (8 pairs x 16 roles). c2r: imag of bins x=0,128 dropped at load.
__global__ void inv_rows4(float* __restrict__ out)
{
    __shared__ __align__(16) char smb[16640];
    float2* gr = (float2*)smb;            // 16 rows x 130
    float2* st = (float2*)smb;            // alias: 8 x 260
    __shared__ float2 stw[128];

    int tid = threadIdx.x;                // 128 threads
    int bid = blockIdx.x;                 // Bb*16
    int b  = bid >> 4;
    int y0 = (bid & 15) << 4;

    stw[tid] = g_tw[tid];
    // load rows y0..y0+15, cols 0..127 (coalesced)
#pragma unroll
    for (int r = 0; r < 16; r++)
        gr[r * 130 + tid] = g_S[(b * 256 + y0 + r) * SSTR + tid];
    __syncthreads();
    if (tid < 16) {                       // col 128 + imag-drop fixups
        gr[tid * 130 + 128] = make_float2(g_S[(b * 256 + y0 + tid) * SSTR + 128].x, 0.0f);
        gr[tid * 130 + 0].y = 0.0f;
    }
    __syncthreads();

    // build Z registers: g = tid>>4 (0..7), t = tid&15 — all 128 active
    int g = tid >> 4, t = tid & 15;
    const float2* G0 = gr + (2 * g) * 130;
    const float2* G1 = gr + (2 * g + 1) * 130;
    float2 z[16];
#pragma unroll
    for (int i = 0; i < 16; i++) {
        int n = (i << 4) + t;
        float2 zz;
        if (n <= 128) {
            float2 a = G0[n], cc = G1[n];
            zz = make_float2(a.x - cc.y, a.y + cc.x);
        } else {
            int m = 256 - n;
            float2 a = G0[m], cc = G1[m];
            zz = make_float2(a.x + cc.y, cc.x - a.y);
        }
        z[i] = zz;
    }
    __syncthreads();                      // all gr reads done before st overwrite

    fft16_dif(z, stw, true);              // reg i: B[k1 = BR4[i]]
#pragma unroll
    for (int i = 0; i < 16; i++) {
        int k1 = BR4[i];
        st[g * 260 + (k1 << 4) + t] = cmulc(z[i], twget(stw, t * k1));
    }
    __syncthreads();

    float2 c[16];
#pragma unroll
    for (int n2 = 0; n2 < 16; n2++)       // thread role: m = t
        c[n2] = st[g * 260 + (t << 4) + n2];
    fft16_dif(c, stw, true);              // reg i: x[n = t + 16*BR4[i]]
    __syncthreads();
#pragma unroll
    for (int i = 0; i < 16; i++)
        st[g * 260 + (BR4[i] << 4) + t] = c[i];
    __syncthreads();

    // write out: row 2g from .x, row 2g+1 from .y, scaled
    const float norm = 1.0f / 65536.0f;
    for (int i = tid; i < 8 * 256; i += 128) {
        int gg = i >> 8, cc = i & 255;
        float2 v = st[gg * 260 + cc];
        int off0 = (b << 16) | ((y0 + 2 * gg) << 8);
        out[off0 + cc]       = v.x * norm;
        out[off0 + 256 + cc] = v.y * norm;
    }
}

// ---------------- launch -----------------------------------------------------
extern "C" void kernel_launch(void* const* d_in, const int* in_sizes, int n_in,
                              void* d_out, int out_size)
{
    const float* rows   = (const float*)d_in[0];
    const float* shifts = (const float*)d_in[1];
    const float* latent = (const float*)d_in[2];
    const float* coords = (const float*)d_in[3];
    const float* values = (const float*)d_in[4];
    const float* W0     = (const float*)d_in[5];
    const float* b0     = (const float*)d_in[6];
    const float* W1     = (const float*)d_in[7];
    const float* b1     = (const float*)d_in[8];
    const float* W2     = (const float*)d_in[9];
    const float* b2     = (const float*)d_in[10];
    const float* W3     = (const float*)d_in[11];
    const float* b3     = (const float*)d_in[12];
    const float* Wd     = (const float*)d_in[13];
    const float* bd     = (const float*)d_in[14];
    const float* ctf    = (const float*)d_in[15];
    float* out = (float*)d_out;

    prep_kernel<<<1, 128>>>(rows, shifts, latent, W0, b0, W1, b1, W2, b2, W3, b3);
    zero_kernel<<<IMG_ELEMS / 4 / 256, 256>>>();
    scatter_kernel<<<(NPTS + 255) / 256, 256>>>(coords, values, Wd, bd);
    blur_y_reg<<<Bb * 32, 256>>>();
    fwd_fft_rows<<<Bb * 16, 128>>>();
    fft_cols_ctf_k<<<Bb * 9, 256>>>(ctf);
    inv_rows4<<<Bb * 16, 128>>>(out);
}

// round 12
// speedup vs baseline: 1.0365x; 1.0365x over previous
#include <cuda_runtime.h>
#include <cuda_bf16.h>
#include <cstdint>

#define Bb   16
#define LAT  8
#define NPTS 500000
#define XS   256
#define IMG_ELEMS (Bb * XS * XS)   // 1,048,576
#define NXH  129                   // Hermitian half-spectrum width
#define SSTR 132                   // g_S row stride (float2)

// ---------------- device scratch (static, no runtime allocation) ------------
__device__ float  g_img[IMG_ELEMS];            // 4 MB (scatter accumulator)
__device__ float2 g_S[Bb * XS * SSTR];         // 4.3 MB half spectrum [b][y][x]
__device__ float2 g_tw[128];                   // exp(-2*pi*i*k/256)

#define REV8(i) ((int)(__brev((unsigned)(i)) >> 24))
__device__ __constant__ int BR4[16] = {0,8,4,12,2,10,6,14,1,9,5,13,3,11,7,15};

__device__ __forceinline__ float2 cmul(float2 a, float2 b)
{ return make_float2(a.x*b.x - a.y*b.y, a.x*b.y + a.y*b.x); }
__device__ __forceinline__ float2 cmulc(float2 a, float2 b)   // a * conj(b)
{ return make_float2(a.x*b.x + a.y*b.y, a.y*b.x - a.x*b.y); }

__device__ __forceinline__ float2 twget(const float2* stw, int idx)
{
    idx &= 255;
    float2 w = stw[idx & 127];
    if (idx & 128) w = make_float2(-w.x, -w.y);
    return w;
}

// ---------------- zero image (vectorized) + twiddle table -------------------
__global__ void zero_kernel()
{
    int i = blockIdx.x * blockDim.x + threadIdx.x;
    reinterpret_cast<float4*>(g_img)[i] = make_float4(0.f, 0.f, 0.f, 0.f);
    if (blockIdx.x == 0 && threadIdx.x < 128) {
        float ang = -6.283185307179586f * (float)threadIdx.x / 256.0f;
        float s, c;
        sincosf(ang, &s, &c);
        g_tw[threadIdx.x] = make_float2(c, s);
    }
}

// ---------------- scatter with inline prep (bit-identical arithmetic) -------
// Threads t<16 compute rotation rows / shifts / MLP h directly into smem using
// the exact intrinsic sequence of the old prep_kernel (same bits), removing a
// kernel launch and the g_R/g_sh/g_h global round-trip.
__global__ void scatter_kernel(const float* __restrict__ coords,
                               const float* __restrict__ values,
                               const float* __restrict__ Wd,
                               const float* __restrict__ bd,
                               const float* __restrict__ rows,
                               const float* __restrict__ shifts,
                               const float* __restrict__ latent,
                               const float* __restrict__ W0, const float* __restrict__ b0,
                               const float* __restrict__ W1, const float* __restrict__ b1,
                               const float* __restrict__ W2, const float* __restrict__ b2,
                               const float* __restrict__ W3, const float* __restrict__ b3)
{
    __shared__ float sR[Bb*6], sSh[Bb*2], sH[Bb*LAT];
    int t = threadIdx.x;
    if (t < Bb) {
        int b = t;
        float rot = rows[b*3+0], tilt = rows[b*3+1], psi = rows[b*3+2];
        float ca = cosf(rot),  sa = sinf(rot);
        float cb = cosf(tilt), sb = sinf(tilt);
        float cg = cosf(psi),  sg = sinf(psi);
        float cgcb = __fmul_rn(cg, cb);
        sR[b*6+0] = __fsub_rn(__fmul_rn(cgcb, ca), __fmul_rn(sg, sa));
        sR[b*6+1] = __fadd_rn(__fmul_rn(cgcb, sa), __fmul_rn(sg, ca));
        sR[b*6+2] = __fmul_rn(-cg, sb);
        float msgcb = __fmul_rn(-sg, cb);
        sR[b*6+3] = __fsub_rn(__fmul_rn(msgcb, ca), __fmul_rn(cg, sa));
        sR[b*6+4] = __fadd_rn(__fmul_rn(msgcb, sa), __fmul_rn(cg, ca));
        sR[b*6+5] = __fmul_rn(sg, sb);
        sSh[b*2+0] = shifts[b*2+0];
        sSh[b*2+1] = shifts[b*2+1];

        float h[LAT], l[LAT], tv[LAT];
        for (int i = 0; i < LAT; i++) l[i] = latent[b*LAT+i];
        for (int j = 0; j < LAT; j++) {
            float acc = 0.0f;
            for (int i = 0; i < LAT; i++) acc = __fmaf_rn(l[i], W0[i*LAT+j], acc);
            acc = __fadd_rn(acc, b0[j]);
            h[j] = sinf(30.0f * acc);
        }
        const float* Ws[3] = {W1, W2, W3};
        const float* bs[3] = {b1, b2, b3};
        for (int L = 0; L < 3; L++) {
            for (int j = 0; j < LAT; j++) {
                float acc = 0.0f;
                for (int i = 0; i < LAT; i++) acc = __fmaf_rn(h[i], Ws[L][i*LAT+j], acc);
                acc = __fadd_rn(acc, bs[L][j]);
                tv[j] = sinf(acc);
            }
            for (int j = 0; j < LAT; j++) h[j] = __fadd_rn(h[j], tv[j]);
        }
        for (int j = 0; j < LAT; j++) sH[b*LAT+j] = h[j];
    }
    __syncthreads();

    int n = blockIdx.x * blockDim.x + t;
    if (n >= NPTS) return;

    float c0 = coords[3*n+0];
    float c1 = coords[3*n+1];
    float c2 = coords[3*n+2];
    float val = values[n];
    float bdn = bd[n];

    float wd[LAT];
#pragma unroll
    for (int l = 0; l < LAT; l++) wd[l] = Wd[l*NPTS + n];

#pragma unroll
    for (int b = 0; b < Bb; b++) {
        float x = __fmul_rn(sR[b*6+0], c0);
        x = __fmaf_rn(sR[b*6+1], c1, x);
        x = __fmaf_rn(sR[b*6+2], c2, x);
        float y = __fmul_rn(sR[b*6+3], c0);
        y = __fmaf_rn(sR[b*6+4], c1, y);
        y = __fmaf_rn(sR[b*6+5], c2, y);
        x = __fadd_rn(__fadd_rn(x, sSh[b*2+0]), 128.0f);
        y = __fadd_rn(__fadd_rn(y, sSh[b*2+1]), 128.0f);
        float pxf = fminf(fmaxf(rintf(x), 0.0f), 255.0f);
        float pyf = fminf(fmaxf(rintf(y), 0.0f), 255.0f);
        int px = (int)pxf;
        int py = (int)pyf;

        float d = 0.0f;
#pragma unroll
        for (int l = 0; l < LAT; l++) d = __fmaf_rn(sH[b*LAT+l], wd[l], d);
        float contrib = __fadd_rn(val, __fadd_rn(d, bdn));

        int idx = (b << 16) | (py << 8) | px;
        atomicAdd(&g_img[idx], contrib);
    }
}

// ---------------- register-resident FFT16 (DIF, bitrev output) --------------
__device__ __forceinline__ void fft16_dif(float2* r, const float2* stw, bool conj_tw)
{
#pragma unroll
    for (int st = 0; st < 4; st++) {
        int half = 8 >> st;
#pragma unroll
        for (int base = 0; base < 16; base += 16 >> st) {
#pragma unroll
            for (int k = 0; k < 8; k++) {
                if (k < half) {
                    int i0 = base + k, i1 = i0 + half;
                    float2 u = r[i0], v = r[i1];
                    r[i0] = make_float2(u.x + v.x, u.y + v.y);
                    float2 d = make_float2(u.x - v.x, u.y - v.y);
                    float2 tw = stw[k << (4 + st)];      // W16^(k*2^st)
                    r[i1] = conj_tw ? cmulc(d, tw) : cmul(d, tw);
                }
            }
        }
    }
}

// DIT with conjugate twiddles: bit-reversed input -> natural output (inverse).
__device__ __forceinline__ void fft16_dit_conj(float2* r, const float2* stw)
{
#pragma unroll
    for (int st = 0; st < 4; st++) {
        int half = 1 << st;
#pragma unroll
        for (int base = 0; base < 16; base += 2 << st) {
#pragma unroll
            for (int k = 0; k < 8; k++) {
                if (k < half) {
                    int i0 = base + k, i1 = i0 + half;
                    float2 tw = stw[k << (7 - st)];
                    float2 u = r[i0];
                    float2 t = cmulc(r[i1], tw);
                    r[i0] = make_float2(u.x + t.x, u.y + t.y);
                    r[i1] = make_float2(u.x - t.x, u.y - t.y);
                }
            }
        }
    }
}

// ---------------- fused blur + forward row FFT, 8 rows/block ----------------
// 256 threads, grid Bb*32 = 512. Blur MAC order bit-identical. float4 halo.
#define GW0 0.39905027f
#define GW1 0.24203622f
#define GW2 0.05400558f
#define GW3 0.00443305f

__global__ void fwd_rows_blur3()
{
    __shared__ __align__(16) char smb[14336 + 8448];
    float*  raw   = (float*)smb;                    // 14 x 256 floats
    float*  ybl   = (float*)(smb + 14336);          // 8 x 264 floats
    float2* stage = (float2*)smb;                   // alias raw: 4 x 260 float2
    float2* zbuf  = (float2*)(smb + 14336);         // alias ybl: 4 x 260 float2
    __shared__ float2 stw[128];
    const float w[7] = {GW3, GW2, GW1, GW0, GW1, GW2, GW3};

    int tid = threadIdx.x;               // 256 threads
    int bid = blockIdx.x;                // Bb*32
    int b  = bid >> 5;
    int y0 = (bid & 31) << 3;

    if (tid < 128) stw[tid] = g_tw[tid];
    if (tid < 48) {                      // zero ybl col borders (8 rows x 6)
        int r = tid / 6, p = tid - r * 6;
        int col = (p < 3) ? p : (256 + p);
        ybl[r * 264 + col] = 0.0f;
    }
    // load 14 halo rows as float4 (coalesced, zero outside)
    const float4* img4 = reinterpret_cast<const float4*>(g_img);
    float4* raw4 = reinterpret_cast<float4*>(raw);
    for (int i = tid; i < 14 * 64; i += 256) {
        int r = i >> 6, c4 = i & 63;
        int gy = y0 + r - 3;
        float4 v = make_float4(0.f, 0.f, 0.f, 0.f);
        if (gy >= 0 && gy < XS)
            v = img4[(b << 14) | (gy << 6) | c4];
        raw4[i] = v;
    }
    __syncthreads();

    // y-pass: 8 rows x 256 cols
    for (int i = tid; i < 8 * 256; i += 256) {
        int r = i >> 8, c = i & 255;
        float acc = 0.0f;
#pragma unroll
        for (int d = 0; d < 7; d++)
            acc += w[d] * raw[((r + d) << 8) | c];
        ybl[r * 264 + 3 + c] = acc;
    }
    __syncthreads();

    // x-pass + pack row pairs (stage aliases raw; raw reads finished)
    for (int i = tid; i < 4 * 256; i += 256) {
        int g = i >> 8, c = i & 255;
        float a0 = 0.0f, a1 = 0.0f;
#pragma unroll
        for (int d = 0; d < 7; d++) {
            a0 += w[d] * ybl[(2 * g)     * 264 + c + d];
            a1 += w[d] * ybl[(2 * g + 1) * 264 + c + d];
        }
        stage[g * 260 + c] = make_float2(a0, a1);
    }
    __syncthreads();

    // four-step FFT256 on 4 pairs: roles tid<64 (g = tid>>4, t = tid&15)
    bool act = (tid < 64);
    int g = tid >> 4, t = tid & 15;
    float2 r[16];
    if (act) {
#pragma unroll
        for (int n1 = 0; n1 < 16; n1++)
            r[n1] = stage[g * 260 + (n1 << 4) + t];
        fft16_dif(r, stw, false);        // reg i: A[k1 = BR4[i]]
        // thread owns column t exclusively -> safe in-place transpose write
#pragma unroll
        for (int i = 0; i < 16; i++) {
            int k1 = BR4[i];
            stage[g * 260 + (k1 << 4) + t] = cmul(r[i], twget(stw, t * k1));
        }
    }
    __syncthreads();

    float2 c[16];
    if (act) {
#pragma unroll
        for (int n2 = 0; n2 < 16; n2++)  // thread role: k1 = t
            c[n2] = stage[g * 260 + (t << 4) + n2];
        fft16_dif(c, stw, false);        // reg i: Z[k = t + 16*BR4[i]]
#pragma unroll
        for (int i = 0; i < 16; i++)
            zbuf[g * 260 + (BR4[i] << 4) + t] = c[i];
    }
    __syncthreads();

    // Hermitian unpack; coalesced stores (4 pairs x 128 x-values)
    for (int i = tid; i < 4 * 128; i += 256) {
        int gg = i >> 7, x = i & 127;
        float2 Z  = zbuf[gg * 260 + x];
        float2 Zm = zbuf[gg * 260 + ((256 - x) & 255)];
        float2 F0 = make_float2(0.5f * (Z.x + Zm.x), 0.5f * (Z.y - Zm.y));
        float2 F1 = make_float2(0.5f * (Z.y + Zm.y), 0.5f * (Zm.x - Z.x));
        int r0 = (b * 256 + y0 + 2 * gg) * SSTR;
        g_S[r0 + x]        = F0;
        g_S[r0 + SSTR + x] = F1;
    }
    if (tid < 4) {                       // x = 128 (Nyquist)
        float2 Zn = zbuf[tid * 260 + 128];
        int r0 = (b * 256 + y0 + 2 * tid) * SSTR;
        g_S[r0 + 128]        = make_float2(Zn.x, 0.0f);
        g_S[r0 + SSTR + 128] = make_float2(Zn.y, 0.0f);
    }
}

// ---------------- column pipeline: four-step 16x16, 16 x-cols per block ------
__global__ void fft_cols_ctf_k(const float* __restrict__ ctf)
{
    __shared__ float2 sm[256 * 17];
    __shared__ float2 stw[128];
    int t  = threadIdx.x;                 // 256
    int xi = t & 15, tb = t >> 4;
    int bid = blockIdx.x;                 // b*9 + tile
    int b = bid / 9, tile = bid - b * 9;
    int x = (tile << 4) + xi;
    bool xok = (x <= 128);
    if (t < 128) stw[t] = g_tw[t];
    __syncthreads();

    float2 r[16];
#pragma unroll
    for (int n1 = 0; n1 < 16; n1++)
        r[n1] = xok ? g_S[(b * 256 + (n1 << 4) + tb) * SSTR + x]
                    : make_float2(0.f, 0.f);
    fft16_dif(r, stw, false);

#pragma unroll
    for (int i = 0; i < 16; i++) {
        int k1 = BR4[i];
        sm[(k1 * 16 + tb) * 17 + xi] = cmul(r[i], twget(stw, tb * k1));
    }
    __syncthreads();

    float2 c[16];
#pragma unroll
    for (int n2 = 0; n2 < 16; n2++)
        c[n2] = sm[(tb * 16 + n2) * 17 + xi];
    fft16_dif(c, stw, false);

#pragma unroll
    for (int i = 0; i < 16; i++) {
        int y = tb + (BR4[i] << 4);
        float cc = xok ? ctf[(b * 256 + y) * NXH + x] : 0.0f;
        c[i].x *= cc; c[i].y *= cc;
    }

    fft16_dit_conj(c, stw);
#pragma unroll
    for (int n2 = 0; n2 < 16; n2++)
        c[n2] = cmulc(c[n2], twget(stw, tb * n2));
    __syncthreads();
#pragma unroll
    for (int n2 = 0; n2 < 16; n2++)
        sm[(n2 * 16 + tb) * 17 + xi] = c[n2];
    __syncthreads();

    float2 e[16];
#pragma unroll
    for (int k1 = 0; k1 < 16; k1++)
        e[k1] = sm[(tb * 16 + k1) * 17 + xi];
    fft16_dif(e, stw, true);

#pragma unroll
    for (int i = 0; i < 16; i++) {
        int y = (BR4[i] << 4) + tb;
        if (xok) g_S[(b * 256 + y) * SSTR + x] = e[i];
    }
}

// ---------------- inverse row FFT: four-step, 8 rows/block ------------------
// 128 threads, grid Bb*32 = 512. c2r: imag of bins x=0,128 dropped at load.
__global__ void inv_rows3(float* __restrict__ out)
{
    __shared__ __align__(16) char smb[8320];
    float2* gr = (float2*)smb;            // 8 rows x 130
    float2* st = (float2*)smb;            // alias: 4 x 260
    __shared__ float2 stw[128];

    int tid = threadIdx.x;                // 128 threads
    int bid = blockIdx.x;                 // Bb*32
    int b  = bid >> 5;
    int y0 = (bid & 31) << 3;

    stw[tid] = g_tw[tid];
    // load rows y0..y0+7, cols 0..127 (coalesced)
#pragma unroll
    for (int r = 0; r < 8; r++)
        gr[r * 130 + tid] = g_S[(b * 256 + y0 + r) * SSTR + tid];
    __syncthreads();
    if (tid < 8) {                        // col 128 + imag-drop fixups
        gr[tid * 130 + 128] = make_float2(g_S[(b * 256 + y0 + tid) * SSTR + 128].x, 0.0f);
        gr[tid * 130 + 0].y = 0.0f;
    }
    __syncthreads();

    // build Z registers: roles tid<64 (g = tid>>4, t = tid&15)
    bool act = (tid < 64);
    int g = tid >> 4, t = tid & 15;
    float2 z[16];
    if (act) {
        const float2* G0 = gr + (2 * g) * 130;
        const float2* G1 = gr + (2 * g + 1) * 130;
#pragma unroll
        for (int i = 0; i < 16; i++) {
            int n = (i << 4) + t;
            float2 zz;
            if (n <= 128) {
                float2 a = G0[n], cc = G1[n];
                zz = make_float2(a.x - cc.y, a.y + cc.x);
            } else {
                int m = 256 - n;
                float2 a = G0[m], cc = G1[m];
                zz = make_float2(a.x + cc.y, cc.x - a.y);
            }
            z[i] = zz;
        }
    }
    __syncthreads();                      // all gr reads done before st overwrite

    if (act) {
        fft16_dif(z, stw, true);          // reg i: B[k1 = BR4[i]]
#pragma unroll
        for (int i = 0; i < 16; i++) {
            int k1 = BR4[i];
            st[g * 260 + (k1 << 4) + t] = cmulc(z[i], twget(stw, t * k1));
        }
    }
    __syncthreads();

    float2 c[16];
    if (act) {
#pragma unroll
        for (int n2 = 0; n2 < 16; n2++)   // thread role: m = t
            c[n2] = st[g * 260 + (t << 4) + n2];
        fft16_dif(c, stw, true);          // reg i: x[n = t + 16*BR4[i]]
#pragma unroll
        for (int i = 0; i < 16; i++)
            st[g * 260 + (BR4[i] << 4) + t] = c[i];
    }
    __syncthreads();

    // write out: row 2g from .x, row 2g+1 from .y, scaled
    const float norm = 1.0f / 65536.0f;
    for (int i = tid; i < 4 * 256; i += 128) {
        int gg = i >> 8, cc = i & 255;
        float2 v = st[gg * 260 + cc];
        int off0 = (b << 16) | ((y0 + 2 * gg) << 8);
        out[off0 + cc]       = v.x * norm;
        out[off0 + 256 + cc] = v.y * norm;
    }
}

// ---------------- launch -----------------------------------------------------
extern "C" void kernel_launch(void* const* d_in, const int* in_sizes, int n_in,
                              void* d_out, int out_size)
{
    const float* rows   = (const float*)d_in[0];
    const float* shifts = (const float*)d_in[1];
    const float* latent = (const float*)d_in[2];
    const float* coords = (const float*)d_in[3];
    const float* values = (const float*)d_in[4];
    const float* W0     = (const float*)d_in[5];
    const float* b0     = (const float*)d_in[6];
    const float* W1     = (const float*)d_in[7];
    const float* b1     = (const float*)d_in[8];
    const float* W2     = (const float*)d_in[9];
    const float* b2     = (const float*)d_in[10];
    const float* W3     = (const float*)d_in[11];
    const float* b3     = (const float*)d_in[12];
    const float* Wd     = (const float*)d_in[13];
    const float* bd     = (const float*)d_in[14];
    const float* ctf    = (const float*)d_in[15];
    float* out = (float*)d_out;

    zero_kernel<<<IMG_ELEMS / 4 / 256, 256>>>();
    scatter_kernel<<<(NPTS + 255) / 256, 256>>>(coords, values, Wd, bd,
                                                rows, shifts, latent,
                                                W0, b0, W1, b1, W2, b2, W3, b3);
    fwd_rows_blur3<<<Bb * 32, 256>>>();
    fft_cols_ctf_k<<<Bb * 9, 256>>>(ctf);
    inv_rows3<<<Bb * 32, 128>>>(out);
}

// round 14
// speedup vs baseline: 1.0633x; 1.0259x over previous
#include <cuda_runtime.h>
#include <cuda_bf16.h>
#include <cstdint>

#define Bb   16
#define LAT  8
#define NPTS 500000
#define XS   256
#define IMG_ELEMS (Bb * XS * XS)   // 1,048,576
#define NXH  129                   // Hermitian half-spectrum width
#define SSTR 132                   // g_S row stride (float2)

// ---------------- device scratch (static, no runtime allocation) ------------
__device__ float  g_img[IMG_ELEMS];            // 4 MB (scatter accumulator)
__device__ float2 g_S[Bb * XS * SSTR];         // 4.3 MB half spectrum [b][y][x]
__device__ float  g_R[Bb * 6];
__device__ float  g_sh[Bb * 2];
__device__ float  g_h[Bb * LAT];
__device__ float2 g_tw[128];                   // exp(-2*pi*i*k/256)

#define REV8(i) ((int)(__brev((unsigned)(i)) >> 24))
__device__ __constant__ int BR4[16] = {0,8,4,12,2,10,6,14,1,9,5,13,3,11,7,15};

__device__ __forceinline__ float2 cmul(float2 a, float2 b)
{ return make_float2(a.x*b.x - a.y*b.y, a.x*b.y + a.y*b.x); }
__device__ __forceinline__ float2 cmulc(float2 a, float2 b)   // a * conj(b)
{ return make_float2(a.x*b.x + a.y*b.y, a.y*b.x - a.x*b.y); }

__device__ __forceinline__ float2 twget(const float2* stw, int idx)
{
    idx &= 255;
    float2 w = stw[idx & 127];
    if (idx & 128) w = make_float2(-w.x, -w.y);
    return w;
}

// ---------------- zero image (vectorized) + twiddle table -------------------
__global__ void zero_kernel()
{
    int i = blockIdx.x * blockDim.x + threadIdx.x;
    reinterpret_cast<float4*>(g_img)[i] = make_float4(0.f, 0.f, 0.f, 0.f);
    if (blockIdx.x == 0 && threadIdx.x < 128) {
        float ang = -6.283185307179586f * (float)threadIdx.x / 256.0f;
        float s, c;
        sincosf(ang, &s, &c);
        g_tw[threadIdx.x] = make_float2(c, s);
    }
}

// ---------------- prep: rotations, shifts, MLP h (bit-identical) ------------
__global__ void prep_kernel(const float* __restrict__ rows,
                            const float* __restrict__ shifts,
                            const float* __restrict__ latent,
                            const float* __restrict__ W0, const float* __restrict__ b0,
                            const float* __restrict__ W1, const float* __restrict__ b1,
                            const float* __restrict__ W2, const float* __restrict__ b2,
                            const float* __restrict__ W3, const float* __restrict__ b3)
{
    int t = threadIdx.x;
    if (t < Bb) {
        int b = t;
        float rot = rows[b*3+0], tilt = rows[b*3+1], psi = rows[b*3+2];
        float ca = cosf(rot),  sa = sinf(rot);
        float cb = cosf(tilt), sb = sinf(tilt);
        float cg = cosf(psi),  sg = sinf(psi);
        float cgcb = __fmul_rn(cg, cb);
        g_R[b*6+0] = __fsub_rn(__fmul_rn(cgcb, ca), __fmul_rn(sg, sa));
        g_R[b*6+1] = __fadd_rn(__fmul_rn(cgcb, sa), __fmul_rn(sg, ca));
        g_R[b*6+2] = __fmul_rn(-cg, sb);
        float msgcb = __fmul_rn(-sg, cb);
        g_R[b*6+3] = __fsub_rn(__fmul_rn(msgcb, ca), __fmul_rn(cg, sa));
        g_R[b*6+4] = __fadd_rn(__fmul_rn(msgcb, sa), __fmul_rn(cg, ca));
        g_R[b*6+5] = __fmul_rn(sg, sb);
        g_sh[b*2+0] = shifts[b*2+0];
        g_sh[b*2+1] = shifts[b*2+1];

        float h[LAT], l[LAT], tv[LAT];
        for (int i = 0; i < LAT; i++) l[i] = latent[b*LAT+i];
        for (int j = 0; j < LAT; j++) {
            float acc = 0.0f;
            for (int i = 0; i < LAT; i++) acc = __fmaf_rn(l[i], W0[i*LAT+j], acc);
            acc = __fadd_rn(acc, b0[j]);
            h[j] = sinf(30.0f * acc);
        }
        const float* Ws[3] = {W1, W2, W3};
        const float* bs[3] = {b1, b2, b3};
        for (int L = 0; L < 3; L++) {
            for (int j = 0; j < LAT; j++) {
                float acc = 0.0f;
                for (int i = 0; i < LAT; i++) acc = __fmaf_rn(h[i], Ws[L][i*LAT+j], acc);
                acc = __fadd_rn(acc, bs[L][j]);
                tv[j] = sinf(acc);
            }
            for (int j = 0; j < LAT; j++) h[j] = __fadd_rn(h[j], tv[j]);
        }
        for (int j = 0; j < LAT; j++) g_h[b*LAT+j] = h[j];
    }
}

// ---------------- scatter (bit-identical to passing version) ----------------
__global__ void scatter_kernel(const float* __restrict__ coords,
                               const float* __restrict__ values,
                               const float* __restrict__ Wd,
                               const float* __restrict__ bd)
{
    __shared__ float sR[Bb*6], sSh[Bb*2], sH[Bb*LAT];
    int t = threadIdx.x;
    if (t < Bb*6)   sR[t]  = g_R[t];
    if (t < Bb*2)   sSh[t] = g_sh[t];
    if (t < Bb*LAT) sH[t]  = g_h[t];
    __syncthreads();

    int n = blockIdx.x * blockDim.x + t;
    if (n >= NPTS) return;

    float c0 = coords[3*n+0];
    float c1 = coords[3*n+1];
    float c2 = coords[3*n+2];
    float val = values[n];
    float bdn = bd[n];

    float wd[LAT];
#pragma unroll
    for (int l = 0; l < LAT; l++) wd[l] = Wd[l*NPTS + n];

#pragma unroll
    for (int b = 0; b < Bb; b++) {
        float x = __fmul_rn(sR[b*6+0], c0);
        x = __fmaf_rn(sR[b*6+1], c1, x);
        x = __fmaf_rn(sR[b*6+2], c2, x);
        float y = __fmul_rn(sR[b*6+3], c0);
        y = __fmaf_rn(sR[b*6+4], c1, y);
        y = __fmaf_rn(sR[b*6+5], c2, y);
        x = __fadd_rn(__fadd_rn(x, sSh[b*2+0]), 128.0f);
        y = __fadd_rn(__fadd_rn(y, sSh[b*2+1]), 128.0f);
        float pxf = fminf(fmaxf(rintf(x), 0.0f), 255.0f);
        float pyf = fminf(fmaxf(rintf(y), 0.0f), 255.0f);
        int px = (int)pxf;
        int py = (int)pyf;

        float d = 0.0f;
#pragma unroll
        for (int l = 0; l < LAT; l++) d = __fmaf_rn(sH[b*LAT+l], wd[l], d);
        float contrib = __fadd_rn(val, __fadd_rn(d, bdn));

        int idx = (b << 16) | (py << 8) | px;
        atomicAdd(&g_img[idx], contrib);
    }
}

// ---------------- register-resident FFT16 (DIF, bitrev output) --------------
__device__ __forceinline__ void fft16_dif(float2* r, const float2* stw, bool conj_tw)
{
#pragma unroll
    for (int st = 0; st < 4; st++) {
        int half = 8 >> st;
#pragma unroll
        for (int base = 0; base < 16; base += 16 >> st) {
#pragma unroll
            for (int k = 0; k < 8; k++) {
                if (k < half) {
                    int i0 = base + k, i1 = i0 + half;
                    float2 u = r[i0], v = r[i1];
                    r[i0] = make_float2(u.x + v.x, u.y + v.y);
                    float2 d = make_float2(u.x - v.x, u.y - v.y);
                    float2 tw = stw[k << (4 + st)];      // W16^(k*2^st)
                    r[i1] = conj_tw ? cmulc(d, tw) : cmul(d, tw);
                }
            }
        }
    }
}

// DIT with conjugate twiddles: bit-reversed input -> natural output (inverse).
__device__ __forceinline__ void fft16_dit_conj(float2* r, const float2* stw)
{
#pragma unroll
    for (int st = 0; st < 4; st++) {
        int half = 1 << st;
#pragma unroll
        for (int base = 0; base < 16; base += 2 << st) {
#pragma unroll
            for (int k = 0; k < 8; k++) {
                if (k < half) {
                    int i0 = base + k, i1 = i0 + half;
                    float2 tw = stw[k << (7 - st)];
                    float2 u = r[i0];
                    float2 t = cmulc(r[i1], tw);
                    r[i0] = make_float2(u.x + t.x, u.y + t.y);
                    r[i1] = make_float2(u.x - t.x, u.y - t.y);
                }
            }
        }
    }
}

// ---------------- fused blur + forward row FFT, 8 rows/block ----------------
#define GW0 0.39905027f
#define GW1 0.24203622f
#define GW2 0.05400558f
#define GW3 0.00443305f

__global__ void fwd_rows_blur3()
{
    __shared__ __align__(16) char smb[14336 + 8448];
    float*  raw   = (float*)smb;                    // 14 x 256 floats
    float*  ybl   = (float*)(smb + 14336);          // 8 x 264 floats
    float2* stage = (float2*)smb;                   // alias raw: 4 x 260 float2
    float2* zbuf  = (float2*)(smb + 14336);         // alias ybl: 4 x 260 float2
    __shared__ float2 stw[128];
    const float w[7] = {GW3, GW2, GW1, GW0, GW1, GW2, GW3};

    int tid = threadIdx.x;               // 256 threads
    int bid = blockIdx.x;                // Bb*32
    int b  = bid >> 5;
    int y0 = (bid & 31) << 3;

    if (tid < 128) stw[tid] = g_tw[tid];
    if (tid < 48) {                      // zero ybl col borders (8 rows x 6)
        int r = tid / 6, p = tid - r * 6;
        int col = (p < 3) ? p : (256 + p);
        ybl[r * 264 + col] = 0.0f;
    }
    // load 14 halo rows as float4 (coalesced, zero outside)
    const float4* img4 = reinterpret_cast<const float4*>(g_img);
    float4* raw4 = reinterpret_cast<float4*>(raw);
    for (int i = tid; i < 14 * 64; i += 256) {
        int r = i >> 6, c4 = i & 63;
        int gy = y0 + r - 3;
        float4 v = make_float4(0.f, 0.f, 0.f, 0.f);
        if (gy >= 0 && gy < XS)
            v = img4[(b << 14) | (gy << 6) | c4];
        raw4[i] = v;
    }
    __syncthreads();

    // y-pass: 8 rows x 256 cols
    for (int i = tid; i < 8 * 256; i += 256) {
        int r = i >> 8, c = i & 255;
        float acc = 0.0f;
#pragma unroll
        for (int d = 0; d < 7; d++)
            acc += w[d] * raw[((r + d) << 8) | c];
        ybl[r * 264 + 3 + c] = acc;
    }
    __syncthreads();

    // x-pass + pack row pairs (stage aliases raw; raw reads finished)
    for (int i = tid; i < 4 * 256; i += 256) {
        int g = i >> 8, c = i & 255;
        float a0 = 0.0f, a1 = 0.0f;
#pragma unroll
        for (int d = 0; d < 7; d++) {
            a0 += w[d] * ybl[(2 * g)     * 264 + c + d];
            a1 += w[d] * ybl[(2 * g + 1) * 264 + c + d];
        }
        stage[g * 260 + c] = make_float2(a0, a1);
    }
    __syncthreads();

    // four-step FFT256 on 4 pairs: roles tid<64 (g = tid>>4, t = tid&15)
    bool act = (tid < 64);
    int g = tid >> 4, t = tid & 15;
    float2 r[16];
    if (act) {
#pragma unroll
        for (int n1 = 0; n1 < 16; n1++)
            r[n1] = stage[g * 260 + (n1 << 4) + t];
        fft16_dif(r, stw, false);        // reg i: A[k1 = BR4[i]]
        // thread owns column t exclusively -> safe in-place transpose write
#pragma unroll
        for (int i = 0; i < 16; i++) {
            int k1 = BR4[i];
            stage[g * 260 + (k1 << 4) + t] = cmul(r[i], twget(stw, t * k1));
        }
    }
    __syncthreads();

    float2 c[16];
    if (act) {
#pragma unroll
        for (int n2 = 0; n2 < 16; n2++)  // thread role: k1 = t
            c[n2] = stage[g * 260 + (t << 4) + n2];
        fft16_dif(c, stw, false);        // reg i: Z[k = t + 16*BR4[i]]
#pragma unroll
        for (int i = 0; i < 16; i++)
            zbuf[g * 260 + (BR4[i] << 4) + t] = c[i];
    }
    __syncthreads();

    // Hermitian unpack; coalesced stores (4 pairs x 128 x-values)
    for (int i = tid; i < 4 * 128; i += 256) {
        int gg = i >> 7, x = i & 127;
        float2 Z  = zbuf[gg * 260 + x];
        float2 Zm = zbuf[gg * 260 + ((256 - x) & 255)];
        float2 F0 = make_float2(0.5f * (Z.x + Zm.x), 0.5f * (Z.y - Zm.y));
        float2 F1 = make_float2(0.5f * (Z.y + Zm.y), 0.5f * (Zm.x - Z.x));
        int r0 = (b * 256 + y0 + 2 * gg) * SSTR;
        g_S[r0 + x]        = F0;
        g_S[r0 + SSTR + x] = F1;
    }
    if (tid < 4) {                       // x = 128 (Nyquist)
        float2 Zn = zbuf[tid * 260 + 128];
        int r0 = (b * 256 + y0 + 2 * tid) * SSTR;
        g_S[r0 + 128]        = make_float2(Zn.x, 0.0f);
        g_S[r0 + SSTR + 128] = make_float2(Zn.y, 0.0f);
    }
}

// ---------------- column pipeline: four-step 16x16, 16 x-cols per block ------
// ctf values prefetched into registers at kernel entry: they are independent
// of the FFT chain, so their global latency overlaps the first two FFT16s.
__global__ void fft_cols_ctf_k(const float* __restrict__ ctf)
{
    __shared__ float2 sm[256 * 17];
    __shared__ float2 stw[128];
    int t  = threadIdx.x;                 // 256
    int xi = t & 15, tb = t >> 4;
    int bid = blockIdx.x;                 // b*9 + tile
    int b = bid / 9, tile = bid - b * 9;
    int x = (tile << 4) + xi;
    bool xok = (x <= 128);
    if (t < 128) stw[t] = g_tw[t];
    __syncthreads();

    // prefetch ctf for y = tb + 16*j (consumed later as cpre[BR4[i]])
    float cpre[16];
#pragma unroll
    for (int j = 0; j < 16; j++)
        cpre[j] = xok ? ctf[(b * 256 + tb + (j << 4)) * NXH + x] : 0.0f;

    float2 r[16];
#pragma unroll
    for (int n1 = 0; n1 < 16; n1++)
        r[n1] = xok ? g_S[(b * 256 + (n1 << 4) + tb) * SSTR + x]
                    : make_float2(0.f, 0.f);
    fft16_dif(r, stw, false);

#pragma unroll
    for (int i = 0; i < 16; i++) {
        int k1 = BR4[i];
        sm[(k1 * 16 + tb) * 17 + xi] = cmul(r[i], twget(stw, tb * k1));
    }
    __syncthreads();

    float2 c[16];
#pragma unroll
    for (int n2 = 0; n2 < 16; n2++)
        c[n2] = sm[(tb * 16 + n2) * 17 + xi];
    fft16_dif(c, stw, false);

    // ctf multiply at y = tb + 16*BR4[i] (same value/order as before)
#pragma unroll
    for (int i = 0; i < 16; i++) {
        float cc = cpre[BR4[i]];
        c[i].x *= cc; c[i].y *= cc;
    }

    fft16_dit_conj(c, stw);
#pragma unroll
    for (int n2 = 0; n2 < 16; n2++)
        c[n2] = cmulc(c[n2], twget(stw, tb * n2));
    __syncthreads();
#pragma unroll
    for (int n2 = 0; n2 < 16; n2++)
        sm[(n2 * 16 + tb) * 17 + xi] = c[n2];
    __syncthreads();

    float2 e[16];
#pragma unroll
    for (int k1 = 0; k1 < 16; k1++)
        e[k1] = sm[(tb * 16 + k1) * 17 + xi];
    fft16_dif(e, stw, true);

#pragma unroll
    for (int i = 0; i < 16; i++) {
        int y = (BR4[i] << 4) + tb;
        if (xok) g_S[(b * 256 + y) * SSTR + x] = e[i];
    }
}

// ---------------- inverse row FFT: four-step, 8 rows/block ------------------
// 128 threads, grid Bb*32 = 512. c2r: imag of bins x=0,128 dropped at load.
__global__ void inv_rows3(float* __restrict__ out)
{
    __shared__ __align__(16) char smb[8320];
    float2* gr = (float2*)smb;            // 8 rows x 130
    float2* st = (float2*)smb;            // alias: 4 x 260
    __shared__ float2 stw[128];

    int tid = threadIdx.x;                // 128 threads
    int bid = blockIdx.x;                 // Bb*32
    int b  = bid >> 5;
    int y0 = (bid & 31) << 3;

    stw[tid] = g_tw[tid];
    // load rows y0..y0+7, cols 0..127 (coalesced)
#pragma unroll
    for (int r = 0; r < 8; r++)
        gr[r * 130 + tid] = g_S[(b * 256 + y0 + r) * SSTR + tid];
    __syncthreads();
    if (tid < 8) {                        // col 128 + imag-drop fixups
        gr[tid * 130 + 128] = make_float2(g_S[(b * 256 + y0 + tid) * SSTR + 128].x, 0.0f);
        gr[tid * 130 + 0].y = 0.0f;
    }
    __syncthreads();

    // build Z registers: roles tid<64 (g = tid>>4, t = tid&15)
    bool act = (tid < 64);
    int g = tid >> 4, t = tid & 15;
    float2 z[16];
    if (act) {
        const float2* G0 = gr + (2 * g) * 130;
        const float2* G1 = gr + (2 * g + 1) * 130;
#pragma unroll
        for (int i = 0; i < 16; i++) {
            int n = (i << 4) + t;
            float2 zz;
            if (n <= 128) {
                float2 a = G0[n], cc = G1[n];
                zz = make_float2(a.x - cc.y, a.y + cc.x);
            } else {
                int m = 256 - n;
                float2 a = G0[m], cc = G1[m];
                zz = make_float2(a.x + cc.y, cc.x - a.y);
            }
            z[i] = zz;
        }
    }
    __syncthreads();                      // all gr reads done before st overwrite

    if (act) {
        fft16_dif(z, stw, true);          // reg i: B[k1 = BR4[i]]
#pragma unroll
        for (int i = 0; i < 16; i++) {
            int k1 = BR4[i];
            st[g * 260 + (k1 << 4) + t] = cmulc(z[i], twget(stw, t * k1));
        }
    }
    __syncthreads();

    float2 c[16];
    if (act) {
#pragma unroll
        for (int n2 = 0; n2 < 16; n2++)   // thread role: m = t
            c[n2] = st[g * 260 + (t << 4) + n2];
        fft16_dif(c, stw, true);          // reg i: x[n = t + 16*BR4[i]]
#pragma unroll
        for (int i = 0; i < 16; i++)
            st[g * 260 + (BR4[i] << 4) + t] = c[i];
    }
    __syncthreads();

    // write out: row 2g from .x, row 2g+1 from .y, scaled
    const float norm = 1.0f / 65536.0f;
    for (int i = tid; i < 4 * 256; i += 128) {
        int gg = i >> 8, cc = i & 255;
        float2 v = st[gg * 260 + cc];
        int off0 = (b << 16) | ((y0 + 2 * gg) << 8);
        out[off0 + cc]       = v.x * norm;
        out[off0 + 256 + cc] = v.y * norm;
    }
}

// ---------------- launch -----------------------------------------------------
extern "C" void kernel_launch(void* const* d_in, const int* in_sizes, int n_in,
                              void* d_out, int out_size)
{
    const float* rows   = (const float*)d_in[0];
    const float* shifts = (const float*)d_in[1];
    const float* latent = (const float*)d_in[2];
    const float* coords = (const float*)d_in[3];
    const float* values = (const float*)d_in[4];
    const float* W0     = (const float*)d_in[5];
    const float* b0     = (const float*)d_in[6];
    const float* W1     = (const float*)d_in[7];
    const float* b1     = (const float*)d_in[8];
    const float* W2     = (const float*)d_in[9];
    const float* b2     = (const float*)d_in[10];
    const float* W3     = (const float*)d_in[11];
    const float* b3     = (const float*)d_in[12];
    const float* Wd     = (const float*)d_in[13];
    const float* bd     = (const float*)d_in[14];
    const float* ctf    = (const float*)d_in[15];
    float* out = (float*)d_out;

    zero_kernel<<<IMG_ELEMS / 4 / 256, 256>>>();
    prep_kernel<<<1, 128>>>(rows, shifts, latent, W0, b0, W1, b1, W2, b2, W3, b3);
    scatter_kernel<<<(NPTS + 255) / 256, 256>>>(coords, values, Wd, bd);
    fwd_rows_blur3<<<Bb * 32, 256>>>();
    fft_cols_ctf_k<<<Bb * 9, 256>>>(ctf);
    inv_rows3<<<Bb * 32, 128>>>(out);
}